// round 1
// baseline (speedup 1.0000x reference)
#include <cuda_runtime.h>
#include <math.h>

#define NR   8192
#define DIMK 512
#define DKC  128
#define DVC  128
#define NCH  128
#define CHS  64      // NCH*CHS == NR

// ---------------- scratch (device globals; no allocation) ----------------
__device__ float  g_u1[DIMK], g_u2[DIMK];
__device__ float  g_d1, g_d2;
__device__ float  g_v[NR * DVC];
__device__ float  g_ssrc[NR];
__device__ float  g_t[NR];
__device__ float  g_tS[NR];
__device__ int    g_idx[NR];
__device__ float  g_w1[NR], g_w2[NR];
__device__ float  g_zSuf1[NR + 1], g_zPre2[NR + 1];
__device__ float  g_A1[(NR + 1) * DVC];   // local pre1 -> suffix1
__device__ float  g_A2[(NR + 1) * DVC];   // local pre2 -> prefix2
__device__ double g_cT1[NCH * DVC], g_cT2[NCH * DVC];
__device__ double g_cP1[NCH * DVC], g_cP2[NCH * DVC];
__device__ double g_Tot1[DVC], g_Tot2[DVC];

// ---------------- 0: fold a into W: u1 = W^T a[:dk], u2 = W^T a[dk:] ------
__global__ void prep_k(const float* __restrict__ W, const float* __restrict__ b,
                       const float* __restrict__ a) {
    int j = threadIdx.x;  // 0..511
    float u1 = 0.f, u2 = 0.f;
    #pragma unroll 8
    for (int k = 0; k < DKC; k++) {
        float w = W[k * DIMK + j];
        u1 += w * a[k];
        u2 += w * a[DKC + k];
    }
    g_u1[j] = u1;
    g_u2[j] = u2;
    if (j < 2) {
        float d = 0.f;
        const float* av = a + (j ? DKC : 0);
        for (int k = 0; k < DKC; k++) d += b[k] * av[k];
        if (j == 0) g_d1 = d; else g_d2 = d;
    }
}

// ---------------- 1: v = x @ Wv^T + bv  (fp32 tiled GEMM, BM=32, BN=128) --
__global__ void __launch_bounds__(256) gemm_v_k(const float* __restrict__ x,
                                                const float* __restrict__ Wv,
                                                const float* __restrict__ bv) {
    __shared__ float xs[32][33];
    __shared__ float ws[32][129];
    int tid = threadIdx.x;
    int i0 = blockIdx.x * 32;
    int tr = tid >> 4, tc = tid & 15;
    float acc[2][8];
    #pragma unroll
    for (int r = 0; r < 2; r++)
        #pragma unroll
        for (int u = 0; u < 8; u++) acc[r][u] = 0.f;

    for (int k0 = 0; k0 < DIMK; k0 += 32) {
        #pragma unroll
        for (int i = 0; i < 4; i++) {
            int l = tid + i * 256;
            int r = l >> 5, kk = l & 31;
            xs[r][kk] = x[(i0 + r) * DIMK + k0 + kk];
        }
        #pragma unroll
        for (int i = 0; i < 16; i++) {
            int l = tid + i * 256;
            int c = l >> 5, kk = l & 31;
            ws[kk][c] = Wv[c * DIMK + k0 + kk];
        }
        __syncthreads();
        #pragma unroll
        for (int kk = 0; kk < 32; kk++) {
            float a0 = xs[tr][kk], a1 = xs[tr + 16][kk];
            #pragma unroll
            for (int u = 0; u < 8; u++) {
                float bb = ws[kk][tc + 16 * u];
                acc[0][u] += a0 * bb;
                acc[1][u] += a1 * bb;
            }
        }
        __syncthreads();
    }
    #pragma unroll
    for (int rr = 0; rr < 2; rr++) {
        int r = i0 + tr + 16 * rr;
        #pragma unroll
        for (int u = 0; u < 8; u++) {
            int c = tc + 16 * u;
            g_v[r * DVC + c] = acc[rr][u] + bv[c];
        }
    }
}

// ---------------- 2: s_src = x@u1 + d1, t = x@u2 + d2  (warp per row) ----
__global__ void __launch_bounds__(256) s_k(const float* __restrict__ x) {
    int warp = threadIdx.x >> 5, lane = threadIdx.x & 31;
    int row = blockIdx.x * 8 + warp;
    const float* xr = x + row * DIMK;
    float a1 = 0.f, a2 = 0.f;
    #pragma unroll
    for (int m = lane; m < DIMK; m += 32) {
        float xv = xr[m];
        a1 += xv * g_u1[m];
        a2 += xv * g_u2[m];
    }
    #pragma unroll
    for (int off = 16; off > 0; off >>= 1) {
        a1 += __shfl_down_sync(0xffffffffu, a1, off);
        a2 += __shfl_down_sync(0xffffffffu, a2, off);
    }
    if (lane == 0) {
        g_ssrc[row] = a1 + g_d1;
        g_t[row]    = a2 + g_d2;
    }
}

// ---------------- 3: bitonic sort of (t, index) in one CTA ---------------
__global__ void __launch_bounds__(1024) sort_k() {
    extern __shared__ unsigned char sm[];
    float* key = (float*)sm;                              // 8192*4
    unsigned short* id = (unsigned short*)(sm + NR * 4);  // 8192*2  -> 48KB total
    int tid = threadIdx.x;
    for (int i = tid; i < NR; i += 1024) { key[i] = g_t[i]; id[i] = (unsigned short)i; }
    __syncthreads();
    for (int k = 2; k <= NR; k <<= 1) {
        for (int j = k >> 1; j > 0; j >>= 1) {
            #pragma unroll
            for (int p = 0; p < 8; p++) {
                int i = tid + (p << 10);
                int ixj = i ^ j;
                if (ixj > i) {
                    bool up = ((i & k) == 0);
                    float ki = key[i], kj = key[ixj];
                    if ((ki > kj) == up) {
                        key[i] = kj; key[ixj] = ki;
                        unsigned short t = id[i]; id[i] = id[ixj]; id[ixj] = t;
                    }
                }
            }
            __syncthreads();
        }
    }
    for (int i = tid; i < NR; i += 1024) { g_tS[i] = key[i]; g_idx[i] = (int)id[i]; }
}

// ---------------- 4: scalar weights + scalar prefix/suffix scan ----------
__global__ void __launch_bounds__(1024) zscan_k() {
    __shared__ double sh1[1024], sh2[1024];
    int tid = threadIdx.x;
    float T = g_tS[NR - 1];
    int base = tid * 8;
    float w1l[8], w2l[8];
    double s1 = 0.0, s2 = 0.0;
    #pragma unroll
    for (int e = 0; e < 8; e++) {
        float t = g_tS[base + e];
        float w1 = expf(t - T);
        float w2 = expf(0.01f * (t - T));
        w1l[e] = w1; w2l[e] = w2;
        g_w1[base + e] = w1; g_w2[base + e] = w2;
        s1 += (double)w1; s2 += (double)w2;
    }
    sh1[tid] = s1; sh2[tid] = s2;
    __syncthreads();
    for (int off = 1; off < 1024; off <<= 1) {
        double v1 = (tid >= off) ? sh1[tid - off] : 0.0;
        double v2 = (tid >= off) ? sh2[tid - off] : 0.0;
        __syncthreads();
        sh1[tid] += v1; sh2[tid] += v2;
        __syncthreads();
    }
    double tot1 = sh1[1023], tot2 = sh2[1023];
    double run1 = sh1[tid] - s1, run2 = sh2[tid] - s2;  // exclusive offsets
    #pragma unroll
    for (int e = 0; e < 8; e++) {
        g_zSuf1[base + e] = (float)(tot1 - run1);
        g_zPre2[base + e] = (float)run2;
        run1 += (double)w1l[e];
        run2 += (double)w2l[e];
    }
    if (tid == 0) { g_zSuf1[NR] = 0.f; g_zPre2[NR] = (float)tot2; }
}

// ---------------- 5a: per-chunk local exclusive prefixes + chunk totals --
__global__ void __launch_bounds__(128) scan1_k() {
    int c = blockIdx.x, d = threadIdx.x;
    double a1 = 0.0, a2 = 0.0;
    int k0 = c * CHS;
    #pragma unroll 4
    for (int e = 0; e < CHS; e++) {
        int k = k0 + e;
        float vv = g_v[g_idx[k] * DVC + d];
        g_A1[k * DVC + d] = (float)a1;
        g_A2[k * DVC + d] = (float)a2;
        a1 += (double)(g_w1[k] * vv);
        a2 += (double)(g_w2[k] * vv);
    }
    g_cT1[c * DVC + d] = a1;
    g_cT2[c * DVC + d] = a2;
}

// ---------------- 5b: scan of chunk totals -------------------------------
__global__ void __launch_bounds__(128) scan2_k() {
    int d = threadIdx.x;
    double r1 = 0.0, r2 = 0.0;
    for (int c = 0; c < NCH; c++) {
        g_cP1[c * DVC + d] = r1;
        g_cP2[c * DVC + d] = r2;
        r1 += g_cT1[c * DVC + d];
        r2 += g_cT2[c * DVC + d];
    }
    g_Tot1[d] = r1;
    g_Tot2[d] = r2;
}

// ---------------- 5c: finalize: A1 -> suffix1, A2 -> prefix2 -------------
__global__ void __launch_bounds__(256) scan3_k() {
    long e = (long)blockIdx.x * 256 + threadIdx.x;
    long total = (long)(NR + 1) * DVC;
    if (e >= total) return;
    int d = (int)(e & (DVC - 1));
    int k = (int)(e >> 7);
    if (k == NR) {
        g_A1[e] = 0.f;
        g_A2[e] = (float)g_Tot2[d];
        return;
    }
    int c = k >> 6;
    double suf = (g_Tot1[d] - g_cP1[c * DVC + d]) - (double)g_A1[e];
    g_A1[e] = (float)suf;
    g_A2[e] = (float)(g_cP2[c * DVC + d] + (double)g_A2[e]);
}

// ---------------- 6: per-row combine -------------------------------------
__global__ void __launch_bounds__(128) final_k(float* __restrict__ out) {
    int d = threadIdx.x;
    float T = g_tS[NR - 1];
    #pragma unroll
    for (int rr = 0; rr < 4; rr++) {
        int i = blockIdx.x * 4 + rr;
        float c = g_ssrc[i];
        float thr = -c;
        int lo = 0, hi = NR;
        while (lo < hi) {                     // lower_bound: first tS >= thr
            int mid = (lo + hi) >> 1;
            if (g_tS[mid] < thr) lo = mid + 1; else hi = mid;
        }
        int k = lo;
        double gamma = exp(-0.99 * ((double)c + (double)T));
        double num = (double)g_A1[k * DVC + d] + gamma * (double)g_A2[k * DVC + d];
        double den = (double)g_zSuf1[k]        + gamma * (double)g_zPre2[k];
        out[i * DVC + d] = (float)(num / den);
    }
}

// ---------------- launch --------------------------------------------------
extern "C" void kernel_launch(void* const* d_in, const int* in_sizes, int n_in,
                              void* d_out, int out_size) {
    const float* x  = (const float*)d_in[0];
    const float* W  = (const float*)d_in[1];
    const float* b  = (const float*)d_in[2];
    const float* Wv = (const float*)d_in[3];
    const float* bv = (const float*)d_in[4];
    const float* a  = (const float*)d_in[5];
    float* out = (float*)d_out;

    prep_k<<<1, 512>>>(W, b, a);
    gemm_v_k<<<NR / 32, 256>>>(x, Wv, bv);
    s_k<<<NR / 8, 256>>>(x);
    sort_k<<<1, 1024, NR * 6>>>();     // 48KB dynamic smem (float keys + u16 ids)
    zscan_k<<<1, 1024>>>();
    scan1_k<<<NCH, 128>>>();
    scan2_k<<<1, 128>>>();
    scan3_k<<<((NR + 1) * DVC + 255) / 256, 256>>>();
    final_k<<<NR / 4, 128>>>(out);
}

// round 2
// speedup vs baseline: 1.3253x; 1.3253x over previous
#include <cuda_runtime.h>
#include <math.h>
#include <stdint.h>

#define NR   8192
#define DIMK 512
#define DKC  128
#define DVC  128
#define NCH  128
#define CHS  64      // NCH*CHS == NR
#define NSEG 4
#define SEGL 2048    // NSEG*SEGL == NR

// ---------------- scratch (device globals; no allocation) ----------------
__device__ float    g_u1[DIMK], g_u2[DIMK];
__device__ float    g_d1, g_d2;
__device__ float    g_v[NR * DVC];
__device__ float    g_ssrc[NR];
__device__ float    g_t[NR];
__device__ uint64_t g_key[NR];
__device__ float    g_tS[NR];
__device__ int      g_idx[NR];
__device__ int      g_kq[NR];
__device__ int      g_partR[NSEG * NR], g_partK[NSEG * NR];
__device__ float    g_w1[NR], g_w2[NR];
__device__ float    g_zSuf1[NR + 1], g_zPre2[NR + 1];
__device__ float    g_A1[(NR + 1) * DVC];   // local pre1 -> suffix1
__device__ float    g_A2[(NR + 1) * DVC];   // local pre2 -> prefix2
__device__ double   g_cT1[NCH * DVC], g_cT2[NCH * DVC];
__device__ double   g_cP1[NCH * DVC], g_cP2[NCH * DVC];
__device__ double   g_Tot1[DVC], g_Tot2[DVC];

// ---------------- 0: fold a into W: u1 = W^T a[:dk], u2 = W^T a[dk:] ------
__global__ void prep_k(const float* __restrict__ W, const float* __restrict__ b,
                       const float* __restrict__ a) {
    int j = threadIdx.x;  // 0..511
    float u1 = 0.f, u2 = 0.f;
    #pragma unroll 8
    for (int k = 0; k < DKC; k++) {
        float w = W[k * DIMK + j];
        u1 += w * a[k];
        u2 += w * a[DKC + k];
    }
    g_u1[j] = u1;
    g_u2[j] = u2;
    if (j < 2) {
        float d = 0.f;
        const float* av = a + (j ? DKC : 0);
        for (int k = 0; k < DKC; k++) d += b[k] * av[k];
        if (j == 0) g_d1 = d; else g_d2 = d;
    }
}

// ---------------- 1: v = x @ Wv^T + bv  (fp32, 64x128x16 tiles) ----------
__global__ void __launch_bounds__(256) gemm_v_k(const float* __restrict__ x,
                                                const float* __restrict__ Wv,
                                                const float* __restrict__ bv) {
    __shared__ float xs[16][68];    // xs[k][m]
    __shared__ float ws[16][132];   // ws[k][n]
    int tid = threadIdx.x;
    int i0 = blockIdx.x * 64;
    int tm = tid >> 5, tn = tid & 31;

    float acc[8][4];
    #pragma unroll
    for (int r = 0; r < 8; r++)
        #pragma unroll
        for (int c = 0; c < 4; c++) acc[r][c] = 0.f;

    for (int k0 = 0; k0 < DIMK; k0 += 16) {
        {   // stage x tile 64x16 (transposed into xs[k][m])
            int row = tid >> 2, kq = (tid & 3) * 4;
            float4 xv = *(const float4*)&x[(i0 + row) * DIMK + k0 + kq];
            xs[kq + 0][row] = xv.x; xs[kq + 1][row] = xv.y;
            xs[kq + 2][row] = xv.z; xs[kq + 3][row] = xv.w;
        }
        #pragma unroll
        for (int i = 0; i < 2; i++) {   // stage Wv tile 128x16
            int idx = tid + i * 256;
            int c = idx >> 2, kq = (idx & 3) * 4;
            float4 wv = *(const float4*)&Wv[c * DIMK + k0 + kq];
            ws[kq + 0][c] = wv.x; ws[kq + 1][c] = wv.y;
            ws[kq + 2][c] = wv.z; ws[kq + 3][c] = wv.w;
        }
        __syncthreads();
        #pragma unroll
        for (int kk = 0; kk < 16; kk++) {
            float4 wv = *(float4*)&ws[kk][tn * 4];
            float xr[8];
            *(float4*)&xr[0] = *(float4*)&xs[kk][tm * 8];
            *(float4*)&xr[4] = *(float4*)&xs[kk][tm * 8 + 4];
            #pragma unroll
            for (int r = 0; r < 8; r++) {
                acc[r][0] += xr[r] * wv.x;
                acc[r][1] += xr[r] * wv.y;
                acc[r][2] += xr[r] * wv.z;
                acc[r][3] += xr[r] * wv.w;
            }
        }
        __syncthreads();
    }
    float4 bb = *(const float4*)&bv[tn * 4];
    #pragma unroll
    for (int r = 0; r < 8; r++) {
        int row = i0 + tm * 8 + r;
        float4 o;
        o.x = acc[r][0] + bb.x; o.y = acc[r][1] + bb.y;
        o.z = acc[r][2] + bb.z; o.w = acc[r][3] + bb.w;
        *(float4*)&g_v[row * DVC + tn * 4] = o;
    }
}

// ---- 2: s_src = x@u1+d1, t = x@u2+d2, sortable key -----------------------
__global__ void __launch_bounds__(256) s_k(const float* __restrict__ x) {
    int warp = threadIdx.x >> 5, lane = threadIdx.x & 31;
    int row = blockIdx.x * 8 + warp;
    const float* xr = x + row * DIMK;
    float a1 = 0.f, a2 = 0.f;
    #pragma unroll
    for (int m = lane; m < DIMK; m += 32) {
        float xv = xr[m];
        a1 += xv * g_u1[m];
        a2 += xv * g_u2[m];
    }
    #pragma unroll
    for (int off = 16; off > 0; off >>= 1) {
        a1 += __shfl_down_sync(0xffffffffu, a1, off);
        a2 += __shfl_down_sync(0xffffffffu, a2, off);
    }
    if (lane == 0) {
        float t = a2 + g_d2;
        g_ssrc[row] = a1 + g_d1;
        g_t[row] = t;
        unsigned u = __float_as_uint(t);
        unsigned s = (u & 0x80000000u) ? ~u : (u | 0x80000000u);
        g_key[row] = ((uint64_t)s << 13) | (uint64_t)row;
    }
}

// ---- 3a: rank-by-counting (replaces bitonic sort) ------------------------
// grid = NSEG * (NR/256) = 128 blocks. block b: seg = b&3, elems = (b>>2)*256..
__global__ void __launch_bounds__(256) rank_k() {
    __shared__ uint64_t skey[SEGL];
    __shared__ float    sflt[SEGL];
    int tid = threadIdx.x;
    int seg = blockIdx.x & (NSEG - 1);
    int i   = (blockIdx.x >> 2) * 256 + tid;
    int jb  = seg * SEGL;

    uint64_t mykey = g_key[i];
    float thr = -g_ssrc[i];

    #pragma unroll
    for (int l = 0; l < SEGL / 256; l++) {
        int j = tid + l * 256;
        skey[j] = g_key[jb + j];
        sflt[j] = g_t[jb + j];
    }
    __syncthreads();

    int cnt = 0, kq = 0;
    #pragma unroll 8
    for (int j = 0; j < SEGL; j++) {
        cnt += (skey[j] < mykey);
        kq  += (sflt[j] < thr);
    }
    g_partR[seg * NR + i] = cnt;
    g_partK[seg * NR + i] = kq;
}

// ---- 3b: combine partial counts, scatter to sorted arrays ----------------
__global__ void __launch_bounds__(256) scatter_k() {
    int i = blockIdx.x * 256 + threadIdx.x;
    int r = 0, kq = 0;
    #pragma unroll
    for (int s = 0; s < NSEG; s++) {
        r  += g_partR[s * NR + i];
        kq += g_partK[s * NR + i];
    }
    g_tS[r]  = g_t[i];
    g_idx[r] = i;
    g_kq[i]  = kq;
}

// ---------------- 4: scalar weights + scalar prefix/suffix scan ----------
__global__ void __launch_bounds__(1024) zscan_k() {
    __shared__ double sh1[1024], sh2[1024];
    int tid = threadIdx.x;
    float T = g_tS[NR - 1];
    int base = tid * 8;
    float w1l[8], w2l[8];
    double s1 = 0.0, s2 = 0.0;
    #pragma unroll
    for (int e = 0; e < 8; e++) {
        float t = g_tS[base + e];
        float w1 = expf(t - T);
        float w2 = expf(0.01f * (t - T));
        w1l[e] = w1; w2l[e] = w2;
        g_w1[base + e] = w1; g_w2[base + e] = w2;
        s1 += (double)w1; s2 += (double)w2;
    }
    sh1[tid] = s1; sh2[tid] = s2;
    __syncthreads();
    for (int off = 1; off < 1024; off <<= 1) {
        double v1 = (tid >= off) ? sh1[tid - off] : 0.0;
        double v2 = (tid >= off) ? sh2[tid - off] : 0.0;
        __syncthreads();
        sh1[tid] += v1; sh2[tid] += v2;
        __syncthreads();
    }
    double tot1 = sh1[1023], tot2 = sh2[1023];
    double run1 = sh1[tid] - s1, run2 = sh2[tid] - s2;  // exclusive offsets
    #pragma unroll
    for (int e = 0; e < 8; e++) {
        g_zSuf1[base + e] = (float)(tot1 - run1);
        g_zPre2[base + e] = (float)run2;
        run1 += (double)w1l[e];
        run2 += (double)w2l[e];
    }
    if (tid == 0) { g_zSuf1[NR] = 0.f; g_zPre2[NR] = (float)tot2; }
}

// ---------------- 5a: per-chunk local exclusive prefixes + chunk totals --
__global__ void __launch_bounds__(128) scan1_k() {
    int c = blockIdx.x, d = threadIdx.x;
    double a1 = 0.0, a2 = 0.0;
    int k0 = c * CHS;
    #pragma unroll 4
    for (int e = 0; e < CHS; e++) {
        int k = k0 + e;
        float vv = g_v[g_idx[k] * DVC + d];
        g_A1[k * DVC + d] = (float)a1;
        g_A2[k * DVC + d] = (float)a2;
        a1 += (double)(g_w1[k] * vv);
        a2 += (double)(g_w2[k] * vv);
    }
    g_cT1[c * DVC + d] = a1;
    g_cT2[c * DVC + d] = a2;
}

// ---------------- 5b: scan of chunk totals -------------------------------
__global__ void __launch_bounds__(128) scan2_k() {
    int d = threadIdx.x;
    double r1 = 0.0, r2 = 0.0;
    for (int c = 0; c < NCH; c++) {
        g_cP1[c * DVC + d] = r1;
        g_cP2[c * DVC + d] = r2;
        r1 += g_cT1[c * DVC + d];
        r2 += g_cT2[c * DVC + d];
    }
    g_Tot1[d] = r1;
    g_Tot2[d] = r2;
}

// ---------------- 5c: finalize: A1 -> suffix1, A2 -> prefix2 -------------
__global__ void __launch_bounds__(256) scan3_k() {
    long e = (long)blockIdx.x * 256 + threadIdx.x;
    long total = (long)(NR + 1) * DVC;
    if (e >= total) return;
    int d = (int)(e & (DVC - 1));
    int k = (int)(e >> 7);
    if (k == NR) {
        g_A1[e] = 0.f;
        g_A2[e] = (float)g_Tot2[d];
        return;
    }
    int c = k >> 6;
    double suf = (g_Tot1[d] - g_cP1[c * DVC + d]) - (double)g_A1[e];
    g_A1[e] = (float)suf;
    g_A2[e] = (float)(g_cP2[c * DVC + d] + (double)g_A2[e]);
}

// ---------------- 6: per-row combine -------------------------------------
__global__ void __launch_bounds__(128) final_k(float* __restrict__ out) {
    int d = threadIdx.x;
    float T = g_tS[NR - 1];
    #pragma unroll
    for (int rr = 0; rr < 4; rr++) {
        int i = blockIdx.x * 4 + rr;
        float c = g_ssrc[i];
        int k = g_kq[i];
        double gamma = exp(-0.99 * ((double)c + (double)T));
        double num = (double)g_A1[k * DVC + d] + gamma * (double)g_A2[k * DVC + d];
        double den = (double)g_zSuf1[k]        + gamma * (double)g_zPre2[k];
        out[i * DVC + d] = (float)(num / den);
    }
}

// ---------------- launch --------------------------------------------------
extern "C" void kernel_launch(void* const* d_in, const int* in_sizes, int n_in,
                              void* d_out, int out_size) {
    const float* x  = (const float*)d_in[0];
    const float* W  = (const float*)d_in[1];
    const float* b  = (const float*)d_in[2];
    const float* Wv = (const float*)d_in[3];
    const float* bv = (const float*)d_in[4];
    const float* a  = (const float*)d_in[5];
    float* out = (float*)d_out;

    prep_k<<<1, 512>>>(W, b, a);
    gemm_v_k<<<NR / 64, 256>>>(x, Wv, bv);
    s_k<<<NR / 8, 256>>>(x);
    rank_k<<<NSEG * (NR / 256), 256>>>();
    scatter_k<<<NR / 256, 256>>>();
    zscan_k<<<1, 1024>>>();
    scan1_k<<<NCH, 128>>>();
    scan2_k<<<1, 128>>>();
    scan3_k<<<((NR + 1) * DVC + 255) / 256, 256>>>();
    final_k<<<NR / 4, 128>>>(out);
}

// round 3
// speedup vs baseline: 1.6103x; 1.2151x over previous
#include <cuda_runtime.h>
#include <math.h>
#include <stdint.h>

#define NR   8192
#define DIMK 512
#define DKC  128
#define DVC  128
#define NCH  128
#define CHS  64      // NCH*CHS == NR
#define NSEG 16
#define SEGL 512     // NSEG*SEGL == NR

// ---------------- scratch (device globals; no allocation) ----------------
__device__ float    g_u1[DIMK], g_u2[DIMK];
__device__ float    g_d1, g_d2;
__device__ float    g_v[NR * DVC];
__device__ float    g_ssrc[NR];
__device__ float    g_t[NR];
__device__ uint64_t g_key[NR];
__device__ float    g_tS[NR];
__device__ int      g_idx[NR];
__device__ int      g_kq[NR];
__device__ int      g_partR[NSEG * NR], g_partK[NSEG * NR];
__device__ float    g_w1[NR], g_w2[NR];
__device__ float    g_zSuf1[NR + 1], g_zPre2[NR + 1];
__device__ float    g_A1[NR * DVC];   // local (per-chunk) exclusive prefix, w1*v
__device__ float    g_A2[NR * DVC];   // local (per-chunk) exclusive prefix, w2*v
__device__ double   g_cT1[NCH * DVC], g_cT2[NCH * DVC];
__device__ double   g_cP1[NCH * DVC], g_cP2[NCH * DVC];
__device__ double   g_Tot1[DVC], g_Tot2[DVC];

// ---------------- 0: fold a into W: u1 = W^T a[:dk], u2 = W^T a[dk:] ------
__global__ void prep_k(const float* __restrict__ W, const float* __restrict__ b,
                       const float* __restrict__ a) {
    int j = threadIdx.x;  // 0..511
    float u1 = 0.f, u2 = 0.f;
    #pragma unroll 8
    for (int k = 0; k < DKC; k++) {
        float w = W[k * DIMK + j];
        u1 += w * a[k];
        u2 += w * a[DKC + k];
    }
    g_u1[j] = u1;
    g_u2[j] = u2;
    if (j < 2) {
        float d = 0.f;
        const float* av = a + (j ? DKC : 0);
        for (int k = 0; k < DKC; k++) d += b[k] * av[k];
        if (j == 0) g_d1 = d; else g_d2 = d;
    }
}

// ---------------- 1: v = x @ Wv^T + bv  (fp32, 64x64x16 tiles) -----------
__global__ void __launch_bounds__(256) gemm_v_k(const float* __restrict__ x,
                                                const float* __restrict__ Wv,
                                                const float* __restrict__ bv) {
    __shared__ float xs[16][68];    // xs[k][m]
    __shared__ float ws[16][68];    // ws[k][n]
    int tid = threadIdx.x;
    int i0 = blockIdx.x * 64;
    int n0 = blockIdx.y * 64;
    int tm = tid >> 4, tn = tid & 15;

    float acc[4][4];
    #pragma unroll
    for (int r = 0; r < 4; r++)
        #pragma unroll
        for (int c = 0; c < 4; c++) acc[r][c] = 0.f;

    int srow = tid >> 2, skq = (tid & 3) * 4;
    for (int k0 = 0; k0 < DIMK; k0 += 16) {
        {   // stage x tile 64x16 (transposed into xs[k][m])
            float4 xv = *(const float4*)&x[(i0 + srow) * DIMK + k0 + skq];
            xs[skq + 0][srow] = xv.x; xs[skq + 1][srow] = xv.y;
            xs[skq + 2][srow] = xv.z; xs[skq + 3][srow] = xv.w;
        }
        {   // stage Wv tile 64x16 (transposed into ws[k][n])
            float4 wv = *(const float4*)&Wv[(n0 + srow) * DIMK + k0 + skq];
            ws[skq + 0][srow] = wv.x; ws[skq + 1][srow] = wv.y;
            ws[skq + 2][srow] = wv.z; ws[skq + 3][srow] = wv.w;
        }
        __syncthreads();
        #pragma unroll
        for (int kk = 0; kk < 16; kk++) {
            float4 xr = *(float4*)&xs[kk][tm * 4];
            float4 wv = *(float4*)&ws[kk][tn * 4];
            acc[0][0] += xr.x * wv.x; acc[0][1] += xr.x * wv.y;
            acc[0][2] += xr.x * wv.z; acc[0][3] += xr.x * wv.w;
            acc[1][0] += xr.y * wv.x; acc[1][1] += xr.y * wv.y;
            acc[1][2] += xr.y * wv.z; acc[1][3] += xr.y * wv.w;
            acc[2][0] += xr.z * wv.x; acc[2][1] += xr.z * wv.y;
            acc[2][2] += xr.z * wv.z; acc[2][3] += xr.z * wv.w;
            acc[3][0] += xr.w * wv.x; acc[3][1] += xr.w * wv.y;
            acc[3][2] += xr.w * wv.z; acc[3][3] += xr.w * wv.w;
        }
        __syncthreads();
    }
    float4 bb = *(const float4*)&bv[n0 + tn * 4];
    #pragma unroll
    for (int r = 0; r < 4; r++) {
        int row = i0 + tm * 4 + r;
        float4 o;
        o.x = acc[r][0] + bb.x; o.y = acc[r][1] + bb.y;
        o.z = acc[r][2] + bb.z; o.w = acc[r][3] + bb.w;
        *(float4*)&g_v[row * DVC + n0 + tn * 4] = o;
    }
}

// ---- 2: s_src = x@u1+d1, t = x@u2+d2, sortable key -----------------------
__global__ void __launch_bounds__(256) s_k(const float* __restrict__ x) {
    int warp = threadIdx.x >> 5, lane = threadIdx.x & 31;
    int row = blockIdx.x * 8 + warp;
    const float* xr = x + row * DIMK;
    float a1 = 0.f, a2 = 0.f;
    #pragma unroll
    for (int m = lane; m < DIMK; m += 32) {
        float xv = xr[m];
        a1 += xv * g_u1[m];
        a2 += xv * g_u2[m];
    }
    #pragma unroll
    for (int off = 16; off > 0; off >>= 1) {
        a1 += __shfl_down_sync(0xffffffffu, a1, off);
        a2 += __shfl_down_sync(0xffffffffu, a2, off);
    }
    if (lane == 0) {
        float t = a2 + g_d2;
        g_ssrc[row] = a1 + g_d1;
        g_t[row] = t;
        unsigned u = __float_as_uint(t);
        unsigned s = (u & 0x80000000u) ? ~u : (u | 0x80000000u);
        g_key[row] = ((uint64_t)s << 13) | (uint64_t)row;
    }
}

// ---- 3a: rank-by-counting (vectorized smem, 16 segments) -----------------
// grid = (NR/256) * NSEG = 512 blocks. seg = b & 15, i-group = b >> 4.
__global__ void __launch_bounds__(256) rank_k() {
    __shared__ uint64_t skey[SEGL];
    __shared__ float    sflt[SEGL];
    int tid = threadIdx.x;
    int seg = blockIdx.x & (NSEG - 1);
    int i   = (blockIdx.x >> 4) * 256 + tid;
    int jb  = seg * SEGL;

    uint64_t mykey = g_key[i];
    float thr = -g_ssrc[i];

    #pragma unroll
    for (int l = 0; l < SEGL / 256; l++) {
        int j = tid + l * 256;
        skey[j] = g_key[jb + j];
        sflt[j] = g_t[jb + j];
    }
    __syncthreads();

    const ulonglong2* sk2 = (const ulonglong2*)skey;
    const float4*     sf4 = (const float4*)sflt;
    int cnt = 0, kq = 0;
    #pragma unroll 4
    for (int q = 0; q < SEGL / 4; q++) {
        ulonglong2 ka = sk2[2 * q];
        ulonglong2 kb = sk2[2 * q + 1];
        float4 f = sf4[q];
        cnt += (ka.x < mykey) + (ka.y < mykey) + (kb.x < mykey) + (kb.y < mykey);
        kq  += (f.x < thr) + (f.y < thr) + (f.z < thr) + (f.w < thr);
    }
    g_partR[seg * NR + i] = cnt;
    g_partK[seg * NR + i] = kq;
}

// ---- 3b: combine partial counts, scatter to sorted arrays ----------------
__global__ void __launch_bounds__(256) scatter_k() {
    int i = blockIdx.x * 256 + threadIdx.x;
    int r = 0, kq = 0;
    #pragma unroll
    for (int s = 0; s < NSEG; s++) {
        r  += g_partR[s * NR + i];
        kq += g_partK[s * NR + i];
    }
    g_tS[r]  = g_t[i];
    g_idx[r] = i;
    g_kq[i]  = kq;
}

// ---------------- 4: scalar weights + scalar prefix/suffix scan ----------
__global__ void __launch_bounds__(1024) zscan_k() {
    __shared__ double sh1[1024], sh2[1024];
    int tid = threadIdx.x;
    float T = g_tS[NR - 1];
    int base = tid * 8;
    float w1l[8], w2l[8];
    double s1 = 0.0, s2 = 0.0;
    #pragma unroll
    for (int e = 0; e < 8; e++) {
        float t = g_tS[base + e];
        float w1 = expf(t - T);
        float w2 = expf(0.01f * (t - T));
        w1l[e] = w1; w2l[e] = w2;
        g_w1[base + e] = w1; g_w2[base + e] = w2;
        s1 += (double)w1; s2 += (double)w2;
    }
    sh1[tid] = s1; sh2[tid] = s2;
    __syncthreads();
    for (int off = 1; off < 1024; off <<= 1) {
        double v1 = (tid >= off) ? sh1[tid - off] : 0.0;
        double v2 = (tid >= off) ? sh2[tid - off] : 0.0;
        __syncthreads();
        sh1[tid] += v1; sh2[tid] += v2;
        __syncthreads();
    }
    double tot1 = sh1[1023], tot2 = sh2[1023];
    double run1 = sh1[tid] - s1, run2 = sh2[tid] - s2;  // exclusive offsets
    #pragma unroll
    for (int e = 0; e < 8; e++) {
        g_zSuf1[base + e] = (float)(tot1 - run1);
        g_zPre2[base + e] = (float)run2;
        run1 += (double)w1l[e];
        run2 += (double)w2l[e];
    }
    if (tid == 0) { g_zSuf1[NR] = 0.f; g_zPre2[NR] = (float)tot2; }
}

// ---------------- 5a: per-chunk local exclusive prefixes + chunk totals --
__global__ void __launch_bounds__(128) scan1_k() {
    int c = blockIdx.x, d = threadIdx.x;
    double a1 = 0.0, a2 = 0.0;
    int k0 = c * CHS;
    #pragma unroll 4
    for (int e = 0; e < CHS; e++) {
        int k = k0 + e;
        float vv = g_v[g_idx[k] * DVC + d];
        g_A1[k * DVC + d] = (float)a1;
        g_A2[k * DVC + d] = (float)a2;
        a1 += (double)(g_w1[k] * vv);
        a2 += (double)(g_w2[k] * vv);
    }
    g_cT1[c * DVC + d] = a1;
    g_cT2[c * DVC + d] = a2;
}

// ---------------- 5b: parallel scan of chunk totals (block per d) --------
__global__ void __launch_bounds__(NCH) scan2_k() {
    __shared__ double s1[NCH], s2[NCH];
    int d = blockIdx.x, c = threadIdx.x;
    double v1 = g_cT1[c * DVC + d], v2 = g_cT2[c * DVC + d];
    s1[c] = v1; s2[c] = v2;
    __syncthreads();
    for (int off = 1; off < NCH; off <<= 1) {
        double a = (c >= off) ? s1[c - off] : 0.0;
        double b = (c >= off) ? s2[c - off] : 0.0;
        __syncthreads();
        s1[c] += a; s2[c] += b;
        __syncthreads();
    }
    g_cP1[c * DVC + d] = s1[c] - v1;   // exclusive
    g_cP2[c * DVC + d] = s2[c] - v2;
    if (c == NCH - 1) { g_Tot1[d] = s1[c]; g_Tot2[d] = s2[c]; }
}

// ---------------- 6: per-row combine (scan3 fused in) --------------------
__global__ void __launch_bounds__(128) final_k(float* __restrict__ out) {
    int d = threadIdx.x;
    float T = g_tS[NR - 1];
    #pragma unroll
    for (int rr = 0; rr < 4; rr++) {
        int i = blockIdx.x * 4 + rr;
        float c = g_ssrc[i];
        int k = g_kq[i];
        double gamma = exp(-0.99 * ((double)c + (double)T));
        double suf, pre;
        if (k < NR) {
            int ch = k >> 6;
            suf = (g_Tot1[d] - g_cP1[ch * DVC + d]) - (double)g_A1[k * DVC + d];
            pre = g_cP2[ch * DVC + d] + (double)g_A2[k * DVC + d];
        } else {
            suf = 0.0;
            pre = g_Tot2[d];
        }
        double num = suf + gamma * pre;
        double den = (double)g_zSuf1[k] + gamma * (double)g_zPre2[k];
        out[i * DVC + d] = (float)(num / den);
    }
}

// ---------------- launch --------------------------------------------------
extern "C" void kernel_launch(void* const* d_in, const int* in_sizes, int n_in,
                              void* d_out, int out_size) {
    const float* x  = (const float*)d_in[0];
    const float* W  = (const float*)d_in[1];
    const float* b  = (const float*)d_in[2];
    const float* Wv = (const float*)d_in[3];
    const float* bv = (const float*)d_in[4];
    const float* a  = (const float*)d_in[5];
    float* out = (float*)d_out;

    prep_k<<<1, 512>>>(W, b, a);
    dim3 ggrid(NR / 64, DVC / 64);
    gemm_v_k<<<ggrid, 256>>>(x, Wv, bv);
    s_k<<<NR / 8, 256>>>(x);
    rank_k<<<(NR / 256) * NSEG, 256>>>();
    scatter_k<<<NR / 256, 256>>>();
    zscan_k<<<1, 1024>>>();
    scan1_k<<<NCH, 128>>>();
    scan2_k<<<DVC, NCH>>>();
    final_k<<<NR / 4, 128>>>(out);
}

// round 4
// speedup vs baseline: 1.8586x; 1.1542x over previous
#include <cuda_runtime.h>
#include <math.h>
#include <stdint.h>

#define NR   8192
#define DIMK 512
#define DKC  128
#define DVC  128
#define NCH  128
#define CHS  64      // NCH*CHS == NR
#define NB   16384   // rank buckets
#define STR  132     // padded column stride (129 used: 128 v-cols + 1 weight col)

// ---------------- scratch (device globals; no allocation) ----------------
__device__ float    g_u1[DIMK], g_u2[DIMK];
__device__ float    g_d1, g_d2;
__device__ float    g_v[NR * DVC];
__device__ float    g_ssrc[NR];
__device__ float    g_t[NR];
__device__ unsigned g_s[NR];          // sortable u32 of t
__device__ int      g_b[NR];          // bucket of t
__device__ unsigned g_smin, g_smax;   // sortable min/max of t
__device__ int      g_hist[NB], g_bcnt[NB], g_cum[NB + 1];
__device__ unsigned g_pkey[NR];       // bucket-grouped keys
__device__ int      g_pid[NR];        // bucket-grouped indices
__device__ int      g_idx[NR];        // sorted order -> original index
__device__ int      g_kq[NR];         // per-row threshold rank
__device__ float    g_w1[NR], g_w2[NR];
__device__ float    g_A1[NR * STR];   // per-chunk local exclusive prefix, w1*v
__device__ float    g_A2[NR * STR];   // per-chunk local exclusive prefix, w2*v
__device__ double   g_cT1[NCH * STR], g_cT2[NCH * STR];
__device__ double   g_cP1[NCH * STR], g_cP2[NCH * STR];
__device__ double   g_Tot1[STR], g_Tot2[STR];

__device__ __forceinline__ unsigned f2sort(float f) {
    unsigned u = __float_as_uint(f);
    return (u & 0x80000000u) ? ~u : (u | 0x80000000u);
}
__device__ __forceinline__ float sort2f(unsigned s) {
    unsigned u = (s & 0x80000000u) ? (s & 0x7FFFFFFFu) : ~s;
    return __uint_as_float(u);
}
__device__ __forceinline__ int bucket_of(float t, float tmin, float scale) {
    int b = (int)((t - tmin) * scale);
    if (b < 0) b = 0;
    if (b > NB - 1) b = NB - 1;
    return b;
}

// ---------------- clear: hist/bcnt zeros, min/max sentinels ---------------
__global__ void clear_k() {
    int i = blockIdx.x * 256 + threadIdx.x;
    if (i < NB) { g_hist[i] = 0; g_bcnt[i] = 0; }
    if (i == 0) { g_smin = 0xFFFFFFFFu; g_smax = 0u; }
}

// ---------------- 0: fold a into W --------------------------------------
__global__ void prep_k(const float* __restrict__ W, const float* __restrict__ b,
                       const float* __restrict__ a) {
    int j = threadIdx.x;  // 0..511
    float u1 = 0.f, u2 = 0.f;
    #pragma unroll 8
    for (int k = 0; k < DKC; k++) {
        float w = W[k * DIMK + j];
        u1 += w * a[k];
        u2 += w * a[DKC + k];
    }
    g_u1[j] = u1;
    g_u2[j] = u2;
    if (j < 2) {
        float d = 0.f;
        const float* av = a + (j ? DKC : 0);
        for (int k = 0; k < DKC; k++) d += b[k] * av[k];
        if (j == 0) g_d1 = d; else g_d2 = d;
    }
}

// ---------------- 1: v = x @ Wv^T + bv  (fp32, 64x64x16 tiles) -----------
__global__ void __launch_bounds__(256) gemm_v_k(const float* __restrict__ x,
                                                const float* __restrict__ Wv,
                                                const float* __restrict__ bv) {
    __shared__ float xs[16][68];
    __shared__ float ws[16][68];
    int tid = threadIdx.x;
    int i0 = blockIdx.x * 64;
    int n0 = blockIdx.y * 64;
    int tm = tid >> 4, tn = tid & 15;

    float acc[4][4];
    #pragma unroll
    for (int r = 0; r < 4; r++)
        #pragma unroll
        for (int c = 0; c < 4; c++) acc[r][c] = 0.f;

    int srow = tid >> 2, skq = (tid & 3) * 4;
    for (int k0 = 0; k0 < DIMK; k0 += 16) {
        {
            float4 xv = *(const float4*)&x[(i0 + srow) * DIMK + k0 + skq];
            xs[skq + 0][srow] = xv.x; xs[skq + 1][srow] = xv.y;
            xs[skq + 2][srow] = xv.z; xs[skq + 3][srow] = xv.w;
        }
        {
            float4 wv = *(const float4*)&Wv[(n0 + srow) * DIMK + k0 + skq];
            ws[skq + 0][srow] = wv.x; ws[skq + 1][srow] = wv.y;
            ws[skq + 2][srow] = wv.z; ws[skq + 3][srow] = wv.w;
        }
        __syncthreads();
        #pragma unroll
        for (int kk = 0; kk < 16; kk++) {
            float4 xr = *(float4*)&xs[kk][tm * 4];
            float4 wv = *(float4*)&ws[kk][tn * 4];
            acc[0][0] += xr.x * wv.x; acc[0][1] += xr.x * wv.y;
            acc[0][2] += xr.x * wv.z; acc[0][3] += xr.x * wv.w;
            acc[1][0] += xr.y * wv.x; acc[1][1] += xr.y * wv.y;
            acc[1][2] += xr.y * wv.z; acc[1][3] += xr.y * wv.w;
            acc[2][0] += xr.z * wv.x; acc[2][1] += xr.z * wv.y;
            acc[2][2] += xr.z * wv.z; acc[2][3] += xr.z * wv.w;
            acc[3][0] += xr.w * wv.x; acc[3][1] += xr.w * wv.y;
            acc[3][2] += xr.w * wv.z; acc[3][3] += xr.w * wv.w;
        }
        __syncthreads();
    }
    float4 bb = *(const float4*)&bv[n0 + tn * 4];
    #pragma unroll
    for (int r = 0; r < 4; r++) {
        int row = i0 + tm * 4 + r;
        float4 o;
        o.x = acc[r][0] + bb.x; o.y = acc[r][1] + bb.y;
        o.z = acc[r][2] + bb.z; o.w = acc[r][3] + bb.w;
        *(float4*)&g_v[row * DVC + n0 + tn * 4] = o;
    }
}

// ---- 2: s_src, t, sortable key, block-reduced global min/max ------------
__global__ void __launch_bounds__(256) s_k(const float* __restrict__ x) {
    __shared__ unsigned wmin[8], wmax[8];
    int warp = threadIdx.x >> 5, lane = threadIdx.x & 31;
    int row = blockIdx.x * 8 + warp;
    const float* xr = x + row * DIMK;
    float a1 = 0.f, a2 = 0.f;
    #pragma unroll
    for (int m = lane; m < DIMK; m += 32) {
        float xv = xr[m];
        a1 += xv * g_u1[m];
        a2 += xv * g_u2[m];
    }
    #pragma unroll
    for (int off = 16; off > 0; off >>= 1) {
        a1 += __shfl_down_sync(0xffffffffu, a1, off);
        a2 += __shfl_down_sync(0xffffffffu, a2, off);
    }
    if (lane == 0) {
        float t = a2 + g_d2;
        g_ssrc[row] = a1 + g_d1;
        g_t[row] = t;
        unsigned s = f2sort(t);
        g_s[row] = s;
        wmin[warp] = s; wmax[warp] = s;
    }
    __syncthreads();
    if (threadIdx.x == 0) {
        unsigned mn = wmin[0], mx = wmax[0];
        #pragma unroll
        for (int w = 1; w < 8; w++) {
            mn = min(mn, wmin[w]);
            mx = max(mx, wmax[w]);
        }
        atomicMin(&g_smin, mn);
        atomicMax(&g_smax, mx);
    }
}

// ---- 3a: histogram of buckets -------------------------------------------
__global__ void __launch_bounds__(256) hist_k() {
    int i = blockIdx.x * 256 + threadIdx.x;
    float tmin = sort2f(g_smin), tmax = sort2f(g_smax);
    float range = tmax - tmin;
    float scale = (range > 0.f) ? (float)(NB - 1) / range : 0.f;
    int b = bucket_of(g_t[i], tmin, scale);
    g_b[i] = b;
    atomicAdd(&g_hist[b], 1);
}

// ---- 3b: exclusive scan of 16384-bucket histogram (1 block) -------------
__global__ void __launch_bounds__(1024) hscan_k() {
    __shared__ int sh[1024];
    int tid = threadIdx.x;
    int loc[16];
    int s = 0;
    #pragma unroll
    for (int e = 0; e < 16; e++) {
        loc[e] = s;                       // local exclusive
        s += g_hist[tid * 16 + e];
    }
    sh[tid] = s;
    __syncthreads();
    for (int off = 1; off < 1024; off <<= 1) {
        int v = (tid >= off) ? sh[tid - off] : 0;
        __syncthreads();
        sh[tid] += v;
        __syncthreads();
    }
    int base = sh[tid] - s;               // exclusive block offset
    #pragma unroll
    for (int e = 0; e < 16; e++) g_cum[tid * 16 + e] = base + loc[e];
    if (tid == 1023) g_cum[NB] = sh[1023];
}

// ---- 3c: scatter elements into bucket-grouped arrays --------------------
__global__ void __launch_bounds__(256) place_k() {
    int i = blockIdx.x * 256 + threadIdx.x;
    int b = g_b[i];
    int pos = g_cum[b] + atomicAdd(&g_bcnt[b], 1);
    g_pkey[pos] = g_s[i];
    g_pid[pos]  = i;
}

// ---- 3d: exact rank + threshold rank + weights (deterministic) ----------
__global__ void __launch_bounds__(256) rank_k() {
    int i = blockIdx.x * 256 + threadIdx.x;
    unsigned si = g_s[i];
    int b = g_b[i];
    int lo = g_cum[b], hi = g_cum[b + 1];
    int r = lo;
    for (int p = lo; p < hi; p++) {
        unsigned sj = g_pkey[p];
        int ij = g_pid[p];
        r += (sj < si) || (sj == si && ij < i);
    }
    float T = sort2f(g_smax);
    float t = g_t[i];
    g_idx[r] = i;
    g_w1[r] = expf(t - T);
    g_w2[r] = expf(0.01f * (t - T));

    // threshold rank: kq = #{ t_j < -ssrc_i }
    float thr = -g_ssrc[i];
    unsigned sthr = f2sort(thr);
    float tmin = sort2f(g_smin), tmax = sort2f(g_smax);
    float range = tmax - tmin;
    float scale = (range > 0.f) ? (float)(NB - 1) / range : 0.f;
    int bb = bucket_of(thr, tmin, scale);
    int kq = g_cum[bb];
    int hi2 = g_cum[bb + 1];
    for (int p = g_cum[bb]; p < hi2; p++) kq += (g_pkey[p] < sthr);
    g_kq[i] = kq;
}

// ---- 5a: per-chunk local exclusive prefixes + chunk totals (129 cols) ---
__global__ void __launch_bounds__(160) scan1_k() {
    int c = blockIdx.x, d = threadIdx.x;
    if (d > 128) return;
    double a1 = 0.0, a2 = 0.0;
    int k0 = c * CHS;
    #pragma unroll 4
    for (int e = 0; e < CHS; e++) {
        int k = k0 + e;
        float vv = (d < 128) ? g_v[g_idx[k] * DVC + d] : 1.0f;
        g_A1[k * STR + d] = (float)a1;
        g_A2[k * STR + d] = (float)a2;
        a1 += (double)(g_w1[k] * vv);
        a2 += (double)(g_w2[k] * vv);
    }
    g_cT1[c * STR + d] = a1;
    g_cT2[c * STR + d] = a2;
}

// ---- 5b: parallel scan of chunk totals (block per column) ---------------
__global__ void __launch_bounds__(NCH) scan2_k() {
    __shared__ double s1[NCH], s2[NCH];
    int d = blockIdx.x, c = threadIdx.x;
    double v1 = g_cT1[c * STR + d], v2 = g_cT2[c * STR + d];
    s1[c] = v1; s2[c] = v2;
    __syncthreads();
    for (int off = 1; off < NCH; off <<= 1) {
        double a = (c >= off) ? s1[c - off] : 0.0;
        double b = (c >= off) ? s2[c - off] : 0.0;
        __syncthreads();
        s1[c] += a; s2[c] += b;
        __syncthreads();
    }
    g_cP1[c * STR + d] = s1[c] - v1;   // exclusive
    g_cP2[c * STR + d] = s2[c] - v2;
    if (c == NCH - 1) { g_Tot1[d] = s1[c]; g_Tot2[d] = s2[c]; }
}

// ---- 6: per-row combine (vector + scalar columns) -----------------------
__global__ void __launch_bounds__(128) final_k(float* __restrict__ out) {
    int d = threadIdx.x;
    float T = sort2f(g_smax);
    #pragma unroll
    for (int rr = 0; rr < 4; rr++) {
        int i = blockIdx.x * 4 + rr;
        float c = g_ssrc[i];
        int k = g_kq[i];
        double gamma = exp(-0.99 * ((double)c + (double)T));
        double suf, pre, sufZ, preZ;
        if (k < NR) {
            int ch = k >> 6;
            long cb = (long)ch * STR;
            long kb = (long)k * STR;
            suf  = (g_Tot1[d]   - g_cP1[cb + d])   - (double)g_A1[kb + d];
            pre  =  g_cP2[cb + d]   + (double)g_A2[kb + d];
            sufZ = (g_Tot1[128] - g_cP1[cb + 128]) - (double)g_A1[kb + 128];
            preZ =  g_cP2[cb + 128] + (double)g_A2[kb + 128];
        } else {
            suf = 0.0;  pre = g_Tot2[d];
            sufZ = 0.0; preZ = g_Tot2[128];
        }
        double num = suf  + gamma * pre;
        double den = sufZ + gamma * preZ;
        out[i * DVC + d] = (float)(num / den);
    }
}

// ---------------- launch --------------------------------------------------
extern "C" void kernel_launch(void* const* d_in, const int* in_sizes, int n_in,
                              void* d_out, int out_size) {
    const float* x  = (const float*)d_in[0];
    const float* W  = (const float*)d_in[1];
    const float* b  = (const float*)d_in[2];
    const float* Wv = (const float*)d_in[3];
    const float* bv = (const float*)d_in[4];
    const float* a  = (const float*)d_in[5];
    float* out = (float*)d_out;

    clear_k<<<NB / 256, 256>>>();
    prep_k<<<1, 512>>>(W, b, a);
    dim3 ggrid(NR / 64, DVC / 64);
    gemm_v_k<<<ggrid, 256>>>(x, Wv, bv);
    s_k<<<NR / 8, 256>>>(x);
    hist_k<<<NR / 256, 256>>>();
    hscan_k<<<1, 1024>>>();
    place_k<<<NR / 256, 256>>>();
    rank_k<<<NR / 256, 256>>>();
    scan1_k<<<NCH, 160>>>();
    scan2_k<<<129, NCH>>>();
    final_k<<<NR / 4, 128>>>(out);
}

// round 5
// speedup vs baseline: 2.3829x; 1.2821x over previous
#include <cuda_runtime.h>
#include <math.h>
#include <stdint.h>

#define NR   8192
#define DIMK 512
#define DKC  128
#define DVC  128
#define NCH  256
#define CHS  32      // NCH*CHS == NR
#define NB   16384   // rank buckets
#define STR  132     // padded column stride (129 used: 128 v-cols + 1 weight col)

// ---------------- scratch (device globals; no allocation) ----------------
__device__ float    g_u1[DIMK], g_u2[DIMK];
__device__ float    g_d1, g_d2;
__device__ float    g_v[NR * DVC];
__device__ float    g_ssrc[NR];
__device__ float    g_t[NR];
__device__ unsigned g_s[NR];          // sortable u32 of t
__device__ int      g_b[NR];          // bucket of t
__device__ unsigned g_smin, g_smax;   // sortable min/max of t
__device__ int      g_hist[NB], g_bcnt[NB], g_cum[NB + 1];
__device__ unsigned g_pkey[NR];       // bucket-grouped keys
__device__ int      g_pid[NR];        // bucket-grouped indices
__device__ int      g_idx[NR];        // sorted order -> original index
__device__ int      g_kq[NR];         // per-row threshold rank
__device__ double   g_gamma[NR];      // per-row mixing factor
__device__ float    g_w1[NR], g_w2[NR];
__device__ float    g_A1[NR * STR];   // per-chunk local exclusive prefix, w1*v
__device__ float    g_A2[NR * STR];   // per-chunk local exclusive prefix, w2*v
__device__ double   g_cT1[NCH * STR], g_cT2[NCH * STR];
__device__ double   g_cP1[NCH * STR], g_cP2[NCH * STR];
__device__ double   g_Tot1[STR], g_Tot2[STR];

__device__ __forceinline__ unsigned f2sort(float f) {
    unsigned u = __float_as_uint(f);
    return (u & 0x80000000u) ? ~u : (u | 0x80000000u);
}
__device__ __forceinline__ float sort2f(unsigned s) {
    unsigned u = (s & 0x80000000u) ? (s & 0x7FFFFFFFu) : ~s;
    return __uint_as_float(u);
}
__device__ __forceinline__ int bucket_of(float t, float tmin, float scale) {
    int b = (int)((t - tmin) * scale);
    if (b < 0) b = 0;
    if (b > NB - 1) b = NB - 1;
    return b;
}

// ---------------- 0: clear hist + fold a into W (merged) ------------------
__global__ void __launch_bounds__(512) prep_k(const float* __restrict__ W,
                                              const float* __restrict__ b,
                                              const float* __restrict__ a) {
    int gi = blockIdx.x * 512 + threadIdx.x;
    g_hist[gi] = 0;
    g_bcnt[gi] = 0;
    if (gi == 0) { g_smin = 0xFFFFFFFFu; g_smax = 0u; }
    if (blockIdx.x == 0) {
        int j = threadIdx.x;  // 0..511
        float u1 = 0.f, u2 = 0.f;
        #pragma unroll 8
        for (int k = 0; k < DKC; k++) {
            float w = W[k * DIMK + j];
            u1 += w * a[k];
            u2 += w * a[DKC + k];
        }
        g_u1[j] = u1;
        g_u2[j] = u2;
        if (j < 2) {
            float d = 0.f;
            const float* av = a + (j ? DKC : 0);
            for (int k = 0; k < DKC; k++) d += b[k] * av[k];
            if (j == 0) g_d1 = d; else g_d2 = d;
        }
    }
}

// ---------------- 1: v = x @ Wv^T + bv  (fp32, 64x64x16 tiles) -----------
__global__ void __launch_bounds__(256) gemm_v_k(const float* __restrict__ x,
                                                const float* __restrict__ Wv,
                                                const float* __restrict__ bv) {
    __shared__ float xs[16][68];
    __shared__ float ws[16][68];
    int tid = threadIdx.x;
    int i0 = blockIdx.x * 64;
    int n0 = blockIdx.y * 64;
    int tm = tid >> 4, tn = tid & 15;

    float acc[4][4];
    #pragma unroll
    for (int r = 0; r < 4; r++)
        #pragma unroll
        for (int c = 0; c < 4; c++) acc[r][c] = 0.f;

    int srow = tid >> 2, skq = (tid & 3) * 4;
    for (int k0 = 0; k0 < DIMK; k0 += 16) {
        {
            float4 xv = *(const float4*)&x[(i0 + srow) * DIMK + k0 + skq];
            xs[skq + 0][srow] = xv.x; xs[skq + 1][srow] = xv.y;
            xs[skq + 2][srow] = xv.z; xs[skq + 3][srow] = xv.w;
        }
        {
            float4 wv = *(const float4*)&Wv[(n0 + srow) * DIMK + k0 + skq];
            ws[skq + 0][srow] = wv.x; ws[skq + 1][srow] = wv.y;
            ws[skq + 2][srow] = wv.z; ws[skq + 3][srow] = wv.w;
        }
        __syncthreads();
        #pragma unroll
        for (int kk = 0; kk < 16; kk++) {
            float4 xr = *(float4*)&xs[kk][tm * 4];
            float4 wv = *(float4*)&ws[kk][tn * 4];
            acc[0][0] += xr.x * wv.x; acc[0][1] += xr.x * wv.y;
            acc[0][2] += xr.x * wv.z; acc[0][3] += xr.x * wv.w;
            acc[1][0] += xr.y * wv.x; acc[1][1] += xr.y * wv.y;
            acc[1][2] += xr.y * wv.z; acc[1][3] += xr.y * wv.w;
            acc[2][0] += xr.z * wv.x; acc[2][1] += xr.z * wv.y;
            acc[2][2] += xr.z * wv.z; acc[2][3] += xr.z * wv.w;
            acc[3][0] += xr.w * wv.x; acc[3][1] += xr.w * wv.y;
            acc[3][2] += xr.w * wv.z; acc[3][3] += xr.w * wv.w;
        }
        __syncthreads();
    }
    float4 bb = *(const float4*)&bv[n0 + tn * 4];
    #pragma unroll
    for (int r = 0; r < 4; r++) {
        int row = i0 + tm * 4 + r;
        float4 o;
        o.x = acc[r][0] + bb.x; o.y = acc[r][1] + bb.y;
        o.z = acc[r][2] + bb.z; o.w = acc[r][3] + bb.w;
        *(float4*)&g_v[row * DVC + n0 + tn * 4] = o;
    }
}

// ---- 2: s_src, t, sortable key, block-reduced global min/max ------------
__global__ void __launch_bounds__(256) s_k(const float* __restrict__ x) {
    __shared__ unsigned wmin[8], wmax[8];
    int warp = threadIdx.x >> 5, lane = threadIdx.x & 31;
    int row = blockIdx.x * 8 + warp;
    const float4* xr = (const float4*)(x + row * DIMK);
    const float4* u1v = (const float4*)g_u1;
    const float4* u2v = (const float4*)g_u2;
    float a1 = 0.f, a2 = 0.f;
    #pragma unroll
    for (int m = lane; m < DIMK / 4; m += 32) {
        float4 xv = xr[m];
        float4 w1 = u1v[m];
        float4 w2 = u2v[m];
        a1 += xv.x * w1.x + xv.y * w1.y + xv.z * w1.z + xv.w * w1.w;
        a2 += xv.x * w2.x + xv.y * w2.y + xv.z * w2.z + xv.w * w2.w;
    }
    #pragma unroll
    for (int off = 16; off > 0; off >>= 1) {
        a1 += __shfl_down_sync(0xffffffffu, a1, off);
        a2 += __shfl_down_sync(0xffffffffu, a2, off);
    }
    if (lane == 0) {
        float t = a2 + g_d2;
        g_ssrc[row] = a1 + g_d1;
        g_t[row] = t;
        unsigned s = f2sort(t);
        g_s[row] = s;
        wmin[warp] = s; wmax[warp] = s;
    }
    __syncthreads();
    if (threadIdx.x == 0) {
        unsigned mn = wmin[0], mx = wmax[0];
        #pragma unroll
        for (int w = 1; w < 8; w++) {
            mn = min(mn, wmin[w]);
            mx = max(mx, wmax[w]);
        }
        atomicMin(&g_smin, mn);
        atomicMax(&g_smax, mx);
    }
}

// ---- 3a: histogram of buckets -------------------------------------------
__global__ void __launch_bounds__(256) hist_k() {
    int i = blockIdx.x * 256 + threadIdx.x;
    float tmin = sort2f(g_smin), tmax = sort2f(g_smax);
    float range = tmax - tmin;
    float scale = (range > 0.f) ? (float)(NB - 1) / range : 0.f;
    int b = bucket_of(g_t[i], tmin, scale);
    g_b[i] = b;
    atomicAdd(&g_hist[b], 1);
}

// ---- 3b: exclusive scan of 16384-bucket histogram (1 block) -------------
__global__ void __launch_bounds__(1024) hscan_k() {
    __shared__ int sh[1024];
    int tid = threadIdx.x;
    int loc[16];
    int s = 0;
    #pragma unroll
    for (int e = 0; e < 16; e++) {
        loc[e] = s;                       // local exclusive
        s += g_hist[tid * 16 + e];
    }
    sh[tid] = s;
    __syncthreads();
    for (int off = 1; off < 1024; off <<= 1) {
        int v = (tid >= off) ? sh[tid - off] : 0;
        __syncthreads();
        sh[tid] += v;
        __syncthreads();
    }
    int base = sh[tid] - s;               // exclusive block offset
    #pragma unroll
    for (int e = 0; e < 16; e++) g_cum[tid * 16 + e] = base + loc[e];
    if (tid == 1023) g_cum[NB] = sh[1023];
}

// ---- 3c: scatter elements into bucket-grouped arrays --------------------
__global__ void __launch_bounds__(256) place_k() {
    int i = blockIdx.x * 256 + threadIdx.x;
    int b = g_b[i];
    int pos = g_cum[b] + atomicAdd(&g_bcnt[b], 1);
    g_pkey[pos] = g_s[i];
    g_pid[pos]  = i;
}

// ---- 3d: exact rank + threshold rank + weights + gamma ------------------
__global__ void __launch_bounds__(256) rank_k() {
    int i = blockIdx.x * 256 + threadIdx.x;
    unsigned si = g_s[i];
    int b = g_b[i];
    int lo = g_cum[b], hi = g_cum[b + 1];
    int r = lo;
    for (int p = lo; p < hi; p++) {
        unsigned sj = g_pkey[p];
        int ij = g_pid[p];
        r += (sj < si) || (sj == si && ij < i);
    }
    float T = sort2f(g_smax);
    float t = g_t[i];
    g_idx[r] = i;
    g_w1[r] = expf(t - T);
    g_w2[r] = expf(0.01f * (t - T));

    // per-row gamma (hoisted out of final_k: one double exp per row)
    float c = g_ssrc[i];
    g_gamma[i] = exp(-0.99 * ((double)c + (double)T));

    // threshold rank: kq = #{ t_j < -ssrc_i }
    float thr = -c;
    unsigned sthr = f2sort(thr);
    float tmin = sort2f(g_smin), tmax = sort2f(g_smax);
    float range = tmax - tmin;
    float scale = (range > 0.f) ? (float)(NB - 1) / range : 0.f;
    int bb = bucket_of(thr, tmin, scale);
    int kq = g_cum[bb];
    int hi2 = g_cum[bb + 1];
    for (int p = g_cum[bb]; p < hi2; p++) kq += (g_pkey[p] < sthr);
    g_kq[i] = kq;
}

// ---- 5a: per-chunk local exclusive prefixes + chunk totals (129 cols) ---
__global__ void __launch_bounds__(160) scan1_k() {
    int c = blockIdx.x, d = threadIdx.x;
    if (d > 128) return;
    double a1 = 0.0, a2 = 0.0;
    int k0 = c * CHS;
    #pragma unroll 4
    for (int e = 0; e < CHS; e++) {
        int k = k0 + e;
        float vv = (d < 128) ? g_v[g_idx[k] * DVC + d] : 1.0f;
        g_A1[k * STR + d] = (float)a1;
        g_A2[k * STR + d] = (float)a2;
        a1 += (double)(g_w1[k] * vv);
        a2 += (double)(g_w2[k] * vv);
    }
    g_cT1[c * STR + d] = a1;
    g_cT2[c * STR + d] = a2;
}

// ---- 5b: parallel scan of chunk totals (block per column) ---------------
__global__ void __launch_bounds__(NCH) scan2_k() {
    __shared__ double s1[NCH], s2[NCH];
    int d = blockIdx.x, c = threadIdx.x;
    double v1 = g_cT1[c * STR + d], v2 = g_cT2[c * STR + d];
    s1[c] = v1; s2[c] = v2;
    __syncthreads();
    for (int off = 1; off < NCH; off <<= 1) {
        double a = (c >= off) ? s1[c - off] : 0.0;
        double b = (c >= off) ? s2[c - off] : 0.0;
        __syncthreads();
        s1[c] += a; s2[c] += b;
        __syncthreads();
    }
    g_cP1[c * STR + d] = s1[c] - v1;   // exclusive
    g_cP2[c * STR + d] = s2[c] - v2;
    if (c == NCH - 1) { g_Tot1[d] = s1[c]; g_Tot2[d] = s2[c]; }
}

// ---- 6: per-row combine (vector + scalar columns) -----------------------
__global__ void __launch_bounds__(128) final_k(float* __restrict__ out) {
    int d = threadIdx.x;
    #pragma unroll
    for (int rr = 0; rr < 4; rr++) {
        int i = blockIdx.x * 4 + rr;
        int k = g_kq[i];
        double gamma = g_gamma[i];
        double suf, pre, sufZ, preZ;
        if (k < NR) {
            int ch = k / CHS;
            long cb = (long)ch * STR;
            long kb = (long)k * STR;
            suf  = (g_Tot1[d]   - g_cP1[cb + d])   - (double)g_A1[kb + d];
            pre  =  g_cP2[cb + d]   + (double)g_A2[kb + d];
            sufZ = (g_Tot1[128] - g_cP1[cb + 128]) - (double)g_A1[kb + 128];
            preZ =  g_cP2[cb + 128] + (double)g_A2[kb + 128];
        } else {
            suf = 0.0;  pre = g_Tot2[d];
            sufZ = 0.0; preZ = g_Tot2[128];
        }
        double num = suf  + gamma * pre;
        double den = sufZ + gamma * preZ;
        out[i * DVC + d] = (float)(num / den);
    }
}

// ---------------- launch --------------------------------------------------
extern "C" void kernel_launch(void* const* d_in, const int* in_sizes, int n_in,
                              void* d_out, int out_size) {
    const float* x  = (const float*)d_in[0];
    const float* W  = (const float*)d_in[1];
    const float* b  = (const float*)d_in[2];
    const float* Wv = (const float*)d_in[3];
    const float* bv = (const float*)d_in[4];
    const float* a  = (const float*)d_in[5];
    float* out = (float*)d_out;

    prep_k<<<NB / 512, 512>>>(W, b, a);
    dim3 ggrid(NR / 64, DVC / 64);
    gemm_v_k<<<ggrid, 256>>>(x, Wv, bv);
    s_k<<<NR / 8, 256>>>(x);
    hist_k<<<NR / 256, 256>>>();
    hscan_k<<<1, 1024>>>();
    place_k<<<NR / 256, 256>>>();
    rank_k<<<NR / 256, 256>>>();
    scan1_k<<<NCH, 160>>>();
    scan2_k<<<129, NCH>>>();
    final_k<<<NR / 4, 128>>>(out);
}